// round 3
// baseline (speedup 1.0000x reference)
#include <cuda_runtime.h>

#define EPSF 1e-6f
#define TPB 128
#define MAXBLOCKS 4096
#define BIGKEY 1e30f

__device__ float g_partial[MAXBLOCKS];
__device__ unsigned int g_count = 0;   // atomicInc wraps -> replay-safe

__device__ __forceinline__ float fast_rcp(float x) {
    float r;
    asm("rcp.approx.f32 %0, %1;" : "=f"(r) : "f"(x));
    return r;
}

__global__ __launch_bounds__(TPB)
void poly_iou_kernel(const float* __restrict__ pred,
                     const float* __restrict__ tgt,
                     float* __restrict__ out,
                     int n) {
    int i = blockIdx.x * blockDim.x + threadIdx.x;
    float loss = 0.0f;

    if (i < n) {
        float4 a0 = reinterpret_cast<const float4*>(pred)[2 * i];
        float4 a1 = reinterpret_cast<const float4*>(pred)[2 * i + 1];
        float4 b0 = reinterpret_cast<const float4*>(tgt)[2 * i];
        float4 b1 = reinterpret_cast<const float4*>(tgt)[2 * i + 1];

        float p1x[4] = {a0.x, a0.z, a1.x, a1.z};
        float p1y[4] = {a0.y, a0.w, a1.y, a1.w};
        float p2x[4] = {b0.x, b0.z, b1.x, b1.z};
        float p2y[4] = {b0.y, b0.w, b1.y, b1.w};

        // Shoelace areas (roll(+1) order as reference).
        float s1 = 0.0f, s2 = 0.0f;
        #pragma unroll
        for (int k = 0; k < 4; k++) {
            int km = (k + 3) & 3;
            s1 += p1x[k] * p1y[km] - p1x[km] * p1y[k];
            s2 += p2x[k] * p2y[km] - p2x[km] * p2y[k];
        }
        float area1 = 0.5f * fabsf(s1);
        float area2 = 0.5f * fabsf(s2);

        // 24 fixed candidate slots, register-resident (no dynamic indexing).
        // key[e] == 0.0f marks "valid" until real keys are computed.
        float qx[24], qy[24], key[24];
        int   m = 0;
        float cxs = 0.0f, cys = 0.0f;

        // --- Slots 0..15: edge-pair intersections (i-major, as reference) ---
        #pragma unroll
        for (int e = 0; e < 16; e++) {
            const int ii = e >> 2, jj = e & 3;
            float x1 = p1x[ii], y1 = p1y[ii];
            float x2 = p1x[(ii + 1) & 3], y2 = p1y[(ii + 1) & 3];
            float x3 = p2x[jj], y3 = p2y[jj];
            float x4 = p2x[(jj + 1) & 3], y4 = p2y[(jj + 1) & 3];

            float num   = (x1 - x2) * (y3 - y4) - (y1 - y2) * (x3 - x4);
            float den_t = (x1 - x3) * (y3 - y4) - (y1 - y3) * (x3 - x4);
            float den_u = (x2 - x1) * (y1 - y3) - (y2 - y1) * (x1 - x3);

            float rnum = fast_rcp(num);                  // num=0 -> inf -> false
            float t_ng = den_t * rnum;
            float u_ng = den_u * rnum;
            bool hit = (t_ng > 0.0f) && (t_ng < 1.0f) &&
                       (u_ng > 0.0f) && (u_ng < 1.0f);

            float t = den_t * fast_rcp(num + EPSF);
            float X = x1 + t * (x2 - x1);
            float Y = y1 + t * (y2 - y1);
            qx[e] = X; qy[e] = Y;
            key[e] = hit ? 0.0f : BIGKEY;
            m   += hit;
            cxs += hit ? X : 0.0f;
            cys += hit ? Y : 0.0f;
        }

        // --- Slots 16..19: poly1 vertices inside poly2 ---
        #pragma unroll
        for (int v = 0; v < 4; v++) {
            float x1 = p1x[v], y1 = p1y[v];
            float s = 0.0f;
            #pragma unroll
            for (int jj = 0; jj < 4; jj++) {
                float x3 = p2x[jj], y3 = p2y[jj];
                float x4 = p2x[(jj + 1) & 3], y4 = p2y[(jj + 1) & 3];
                s += fabsf((x3 - x1) * (y4 - y1) - (y3 - y1) * (x4 - x1));
            }
            s *= 0.5f;
            bool inn = fabsf(s - area2) < 0.001f * area2;
            qx[16 + v] = x1; qy[16 + v] = y1;
            key[16 + v] = inn ? 0.0f : BIGKEY;
            m   += inn;
            cxs += inn ? x1 : 0.0f;
            cys += inn ? y1 : 0.0f;
        }

        // --- Slots 20..23: poly2 vertices inside poly1 ---
        #pragma unroll
        for (int v = 0; v < 4; v++) {
            float x3 = p2x[v], y3 = p2y[v];
            float s = 0.0f;
            #pragma unroll
            for (int ii = 0; ii < 4; ii++) {
                float x1 = p1x[ii], y1 = p1y[ii];
                float x2 = p1x[(ii + 1) & 3], y2 = p1y[(ii + 1) & 3];
                s += fabsf((x1 - x3) * (y2 - y3) - (x2 - x3) * (y1 - y3));
            }
            s *= 0.5f;
            bool inn = fabsf(s - area1) < 0.001f * area1;
            qx[20 + v] = x3; qy[20 + v] = y3;
            key[20 + v] = inn ? 0.0f : BIGKEY;
            m   += inn;
            cxs += inn ? x3 : 0.0f;
            cys += inn ? y3 : 0.0f;
        }

        // --- Pseudo-angle keys (strictly monotone with atan2; NaN-proofed) ---
        float invm = fast_rcp((float)(m > 0 ? m : 1));
        float cx = cxs * invm, cy = cys * invm;
        #pragma unroll
        for (int e = 0; e < 24; e++) {
            bool v = (key[e] == 0.0f);
            float dx = qx[e] - cx, dy = qy[e] - cy;
            float t = dy * fast_rcp(fmaxf(fabsf(dx) + fabsf(dy), 1e-30f));
            float pk = (dx >= 0.0f) ? t : ((dy >= 0.0f) ? 2.0f - t : -2.0f - t);
            key[e] = v ? pk : BIGKEY;   // select, never arithmetic on NaN coords
        }

        // --- Stable rank computation + scatter (branch-free) ---
        // rank_k = #{l<k: key_l<=key_k} + #{l>k: key_l<key_k}  == stable argsort pos
        float sx[25], sy[25];
        #pragma unroll
        for (int k = 0; k < 24; k++) {
            int r = 0;
            #pragma unroll
            for (int l = 0; l < 24; l++) {
                if (l == k) continue;
                if (l < k) r += (key[l] <= key[k]);
                else       r += (key[l] <  key[k]);
            }
            sx[r] = qx[k]; sy[r] = qy[k];
        }
        sx[m] = sx[0]; sy[m] = sy[0];   // close the polygon (array has 25 slots)

        // --- Closed shoelace over the first m sorted points (predicated) ---
        float s = 0.0f;
        #pragma unroll
        for (int k = 0; k < 24; k++) {
            float c = sx[k] * sy[k + 1] - sy[k] * sx[k + 1];
            s += (k < m) ? c : 0.0f;
        }
        float overlap = 0.5f * fabsf(s);

        float iou = overlap * fast_rcp(area1 + area2 - overlap + EPSF);
        iou = fminf(fmaxf(iou, EPSF), 1.0f);
        loss = 1.0f - iou;
    }

    // --- Intra-block reduction ---
    #pragma unroll
    for (int off = 16; off > 0; off >>= 1)
        loss += __shfl_down_sync(0xffffffffu, loss, off);

    __shared__ float wsum[TPB / 32];
    int lane = threadIdx.x & 31;
    int wid  = threadIdx.x >> 5;
    if (lane == 0) wsum[wid] = loss;
    __syncthreads();

    if (wid == 0) {
        float v = (lane < TPB / 32) ? wsum[lane] : 0.0f;
        #pragma unroll
        for (int off = TPB / 64; off > 0; off >>= 1)
            v += __shfl_down_sync(0xffffffffu, v, off);
        if (lane == 0) wsum[0] = v;
    }
    __syncthreads();

    // --- Last-block-done final reduction ---
    __shared__ bool is_last;
    if (threadIdx.x == 0) {
        g_partial[blockIdx.x] = wsum[0];
        __threadfence();
        unsigned prev = atomicInc(&g_count, gridDim.x - 1);
        is_last = (prev == gridDim.x - 1);
    }
    __syncthreads();

    if (is_last) {
        double s = 0.0;
        for (int k = threadIdx.x; k < (int)gridDim.x; k += TPB)
            s += (double)g_partial[k];
        #pragma unroll
        for (int off = 16; off > 0; off >>= 1)
            s += __shfl_down_sync(0xffffffffu, s, off);

        __shared__ double dsum[TPB / 32];
        if (lane == 0) dsum[wid] = s;
        __syncthreads();
        if (wid == 0) {
            double v = (lane < TPB / 32) ? dsum[lane] : 0.0;
            #pragma unroll
            for (int off = TPB / 64; off > 0; off >>= 1)
                v += __shfl_down_sync(0xffffffffu, v, off);
            if (lane == 0)
                out[0] = (float)(v / (double)n);
        }
    }
}

extern "C" void kernel_launch(void* const* d_in, const int* in_sizes, int n_in,
                              void* d_out, int out_size) {
    const float* pred = (const float*)d_in[0];
    const float* tgt  = (const float*)d_in[1];
    int n = in_sizes[0] / 8;

    int blocks = (n + TPB - 1) / TPB;
    poly_iou_kernel<<<blocks, TPB>>>(pred, tgt, (float*)d_out, n);
}

// round 4
// speedup vs baseline: 1.5663x; 1.5663x over previous
#include <cuda_runtime.h>

#define EPSF 1e-6f
#define TPB 256
#define MAXBLOCKS 4096

__device__ float g_partial[MAXBLOCKS];
__device__ unsigned int g_count = 0;   // atomicInc wraps to 0 -> graph-replay-safe

__device__ __forceinline__ float fast_rcp(float x) {
    float r;
    asm("rcp.approx.f32 %0, %1;" : "=f"(r) : "f"(x));
    return r;
}

__global__ __launch_bounds__(TPB)
void poly_iou_kernel(const float* __restrict__ pred,
                     const float* __restrict__ tgt,
                     float* __restrict__ out,
                     int n) {
    int i = blockIdx.x * blockDim.x + threadIdx.x;
    float loss = 0.0f;

    if (i < n) {
        float4 a0 = reinterpret_cast<const float4*>(pred)[2 * i];
        float4 a1 = reinterpret_cast<const float4*>(pred)[2 * i + 1];
        float4 b0 = reinterpret_cast<const float4*>(tgt)[2 * i];
        float4 b1 = reinterpret_cast<const float4*>(tgt)[2 * i + 1];

        float p1x[4] = {a0.x, a0.z, a1.x, a1.z};
        float p1y[4] = {a0.y, a0.w, a1.y, a1.w};
        float p2x[4] = {b0.x, b0.z, b1.x, b1.z};
        float p2y[4] = {b0.y, b0.w, b1.y, b1.w};

        // Signed shoelace sums -> areas (same ordering as reference roll(+1)).
        float s1 = 0.0f, s2 = 0.0f;
        #pragma unroll
        for (int k = 0; k < 4; k++) {
            int km = (k + 3) & 3;
            s1 += p1x[k] * p1y[km] - p1x[km] * p1y[k];
            s2 += p2x[k] * p2y[km] - p2x[km] * p2y[k];
        }
        float area1 = 0.5f * fabsf(s1);
        float area2 = 0.5f * fabsf(s2);

        // Orientation of poly2 (convex): sign of one corner cross product.
        float ocr = (p2x[1] - p2x[0]) * (p2y[2] - p2y[1]) -
                    (p2y[1] - p2y[0]) * (p2x[2] - p2x[1]);
        float orient = (ocr >= 0.0f) ? 1.0f : -1.0f;

        // --- Sutherland–Hodgman: clip poly1 by poly2's 4 half-planes ---
        float bufAx[10], bufAy[10], bufBx[10], bufBy[10];
        float *inx = bufAx, *iny = bufAy, *outx = bufBx, *outy = bufBy;
        #pragma unroll
        for (int k = 0; k < 4; k++) { inx[k] = p1x[k]; iny[k] = p1y[k]; }
        int cnt = 4;

        #pragma unroll
        for (int j = 0; j < 4; j++) {
            float ax = p2x[j], ay = p2y[j];
            float ex = (p2x[(j + 1) & 3] - ax) * orient;
            float ey = (p2y[(j + 1) & 3] - ay) * orient;

            // signed distances (inside: >= 0)
            float dv[8];
            #pragma unroll
            for (int k = 0; k < 8; k++)
                dv[k] = ex * (iny[k] - ay) - ey * (inx[k] - ax);

            int oc = 0;
            #pragma unroll
            for (int k = 0; k < 8; k++) {
                if (k < cnt) {
                    int kn = (k + 1 == cnt) ? 0 : k + 1;
                    float dc = dv[k], dn = dv[kn];
                    float cxk = inx[k], cyk = iny[k];
                    bool in_c = (dc >= 0.0f);
                    bool in_n = (dn >= 0.0f);
                    if (in_c) { outx[oc] = cxk; outy[oc] = cyk; oc++; }
                    if (in_c != in_n) {
                        float t = dc * fast_rcp(dc - dn);
                        outx[oc] = cxk + t * (inx[kn] - cxk);
                        outy[oc] = cyk + t * (iny[kn] - cyk);
                        oc++;
                    }
                }
            }
            cnt = oc;
            float* tx = inx; inx = outx; outx = tx;
            float* ty = iny; iny = outy; outy = ty;
        }

        // --- Shoelace of the (already ordered) clipped polygon ---
        float s = 0.0f;
        #pragma unroll
        for (int k = 0; k < 8; k++) {
            if (k < cnt) {
                int kn = (k + 1 == cnt) ? 0 : k + 1;
                s += inx[k] * iny[kn] - iny[k] * inx[kn];
            }
        }
        float overlap = (cnt >= 3) ? 0.5f * fabsf(s) : 0.0f;

        float iou = overlap * fast_rcp(area1 + area2 - overlap + EPSF);
        iou = fminf(fmaxf(iou, EPSF), 1.0f);
        loss = 1.0f - iou;
    }

    // --- Intra-block reduction ---
    #pragma unroll
    for (int off = 16; off > 0; off >>= 1)
        loss += __shfl_down_sync(0xffffffffu, loss, off);

    __shared__ float wsum[TPB / 32];
    int lane = threadIdx.x & 31;
    int wid  = threadIdx.x >> 5;
    if (lane == 0) wsum[wid] = loss;
    __syncthreads();

    if (wid == 0) {
        float v = (lane < TPB / 32) ? wsum[lane] : 0.0f;
        #pragma unroll
        for (int off = TPB / 64; off > 0; off >>= 1)
            v += __shfl_down_sync(0xffffffffu, v, off);
        if (lane == 0) wsum[0] = v;
    }
    __syncthreads();

    // --- Last-block-done final reduction (single launch) ---
    __shared__ bool is_last;
    if (threadIdx.x == 0) {
        g_partial[blockIdx.x] = wsum[0];
        __threadfence();
        unsigned prev = atomicInc(&g_count, gridDim.x - 1);
        is_last = (prev == gridDim.x - 1);
    }
    __syncthreads();

    if (is_last) {
        double s = 0.0;
        for (int k = threadIdx.x; k < (int)gridDim.x; k += TPB)
            s += (double)g_partial[k];
        #pragma unroll
        for (int off = 16; off > 0; off >>= 1)
            s += __shfl_down_sync(0xffffffffu, s, off);

        __shared__ double dsum[TPB / 32];
        if (lane == 0) dsum[wid] = s;
        __syncthreads();
        if (wid == 0) {
            double v = (lane < TPB / 32) ? dsum[lane] : 0.0;
            #pragma unroll
            for (int off = TPB / 64; off > 0; off >>= 1)
                v += __shfl_down_sync(0xffffffffu, v, off);
            if (lane == 0)
                out[0] = (float)(v / (double)n);
        }
    }
}

extern "C" void kernel_launch(void* const* d_in, const int* in_sizes, int n_in,
                              void* d_out, int out_size) {
    const float* pred = (const float*)d_in[0];
    const float* tgt  = (const float*)d_in[1];
    int n = in_sizes[0] / 8;

    int blocks = (n + TPB - 1) / TPB;
    poly_iou_kernel<<<blocks, TPB>>>(pred, tgt, (float*)d_out, n);
}

// round 5
// speedup vs baseline: 3.3016x; 2.1079x over previous
#include <cuda_runtime.h>

#define EPSF 1e-6f
#define TPB 256
#define MAXBLOCKS 4096

__device__ float g_partial[MAXBLOCKS];
__device__ unsigned int g_count = 0;   // atomicInc wraps to 0 -> graph-replay-safe

__device__ __forceinline__ float fast_rcp(float x) {
    float r;
    asm("rcp.approx.f32 %0, %1;" : "=f"(r) : "f"(x));
    return r;
}

// Shared polygon buffers: [slot][tid] layout -> lane k hits bank k, conflict-free.
// B1 = slots 0..6 (7 slots, max stage-2 output), B2 = slots 7..12 (6 slots).
#define NSLOT 13
#define B1 0
#define B2 7

// One Sutherland–Hodgman clip stage: input polygon (cnt <= MAXIN) from shared,
// output appended to shared. Rolling (prev, d_prev) walk: each vertex loaded
// once, one signed distance per vertex.
template <int MAXIN>
__device__ __forceinline__ int clip_stage(
    float ax, float ay, float ex, float ey,
    const float* __restrict__ inX, const float* __restrict__ inY, int cnt,
    float* __restrict__ outX, float* __restrict__ outY)
{
    int oc = 0;
    if (cnt > 0) {
        float pxv = inX[(cnt - 1) * TPB];
        float pyv = inY[(cnt - 1) * TPB];
        float dp  = ex * (pyv - ay) - ey * (pxv - ax);
        #pragma unroll
        for (int k = 0; k < MAXIN; k++) {
            if (k < cnt) {
                float cxv = inX[k * TPB];
                float cyv = inY[k * TPB];
                float dc  = ex * (cyv - ay) - ey * (cxv - ax);
                bool in_p = (dp >= 0.0f);
                bool in_c = (dc >= 0.0f);
                if (in_p != in_c) {                 // edge crosses the plane
                    float t = dp * fast_rcp(dp - dc);
                    outX[oc * TPB] = pxv + t * (cxv - pxv);
                    outY[oc * TPB] = pyv + t * (cyv - pyv);
                    oc++;
                }
                if (in_c) {                         // keep inside vertex
                    outX[oc * TPB] = cxv;
                    outY[oc * TPB] = cyv;
                    oc++;
                }
                pxv = cxv; pyv = cyv; dp = dc;
            }
        }
    }
    return oc;
}

__global__ __launch_bounds__(TPB)
void poly_iou_kernel(const float* __restrict__ pred,
                     const float* __restrict__ tgt,
                     float* __restrict__ out,
                     int n) {
    __shared__ float shx[NSLOT][TPB];
    __shared__ float shy[NSLOT][TPB];

    int i = blockIdx.x * blockDim.x + threadIdx.x;
    int tid = threadIdx.x;
    float loss = 0.0f;

    if (i < n) {
        float4 a0 = reinterpret_cast<const float4*>(pred)[2 * i];
        float4 a1 = reinterpret_cast<const float4*>(pred)[2 * i + 1];
        float4 b0 = reinterpret_cast<const float4*>(tgt)[2 * i];
        float4 b1 = reinterpret_cast<const float4*>(tgt)[2 * i + 1];

        float p1x[4] = {a0.x, a0.z, a1.x, a1.z};
        float p1y[4] = {a0.y, a0.w, a1.y, a1.w};
        float p2x[4] = {b0.x, b0.z, b1.x, b1.z};
        float p2y[4] = {b0.y, b0.w, b1.y, b1.w};

        // Shoelace areas (roll(+1) order, as reference).
        float s1 = 0.0f, s2 = 0.0f;
        #pragma unroll
        for (int k = 0; k < 4; k++) {
            int km = (k + 3) & 3;
            s1 += p1x[k] * p1y[km] - p1x[km] * p1y[k];
            s2 += p2x[k] * p2y[km] - p2x[km] * p2y[k];
        }
        float area1 = 0.5f * fabsf(s1);
        float area2 = 0.5f * fabsf(s2);

        // Orientation of poly2 so "inside" is d >= 0.
        float ocr = (p2x[1] - p2x[0]) * (p2y[2] - p2y[1]) -
                    (p2y[1] - p2y[0]) * (p2x[2] - p2x[1]);
        float orient = (ocr >= 0.0f) ? 1.0f : -1.0f;

        // Clip-edge parameters for poly2's 4 edges.
        float eax[4], eay[4], eex[4], eey[4];
        #pragma unroll
        for (int j = 0; j < 4; j++) {
            eax[j] = p2x[j]; eay[j] = p2y[j];
            eex[j] = (p2x[(j + 1) & 3] - p2x[j]) * orient;
            eey[j] = (p2y[(j + 1) & 3] - p2y[j]) * orient;
        }

        float* b1x = &shx[B1][tid]; float* b1y = &shy[B1][tid];
        float* b2x = &shx[B2][tid]; float* b2y = &shy[B2][tid];

        // --- Stage 0: quad1 (registers) clipped by edge 0 -> B1 (<=5) ---
        int cnt;
        {
            float ax = eax[0], ay = eay[0], ex = eex[0], ey = eey[0];
            float pxv = p1x[3], pyv = p1y[3];
            float dp  = ex * (pyv - ay) - ey * (pxv - ax);
            int oc = 0;
            #pragma unroll
            for (int k = 0; k < 4; k++) {
                float cxv = p1x[k], cyv = p1y[k];
                float dc  = ex * (cyv - ay) - ey * (cxv - ax);
                bool in_p = (dp >= 0.0f);
                bool in_c = (dc >= 0.0f);
                if (in_p != in_c) {
                    float t = dp * fast_rcp(dp - dc);
                    b1x[oc * TPB] = pxv + t * (cxv - pxv);
                    b1y[oc * TPB] = pyv + t * (cyv - pyv);
                    oc++;
                }
                if (in_c) {
                    b1x[oc * TPB] = cxv;
                    b1y[oc * TPB] = cyv;
                    oc++;
                }
                pxv = cxv; pyv = cyv; dp = dc;
            }
            cnt = oc;
        }

        // --- Stage 1: B1 (<=5) -> B2 (<=6) ---
        cnt = clip_stage<5>(eax[1], eay[1], eex[1], eey[1], b1x, b1y, cnt, b2x, b2y);
        // --- Stage 2: B2 (<=6) -> B1 (<=7) ---
        cnt = clip_stage<6>(eax[2], eay[2], eex[2], eey[2], b2x, b2y, cnt, b1x, b1y);

        // --- Stage 3: B1 (<=7), stream emits directly into the shoelace sum ---
        float s = 0.0f;
        int oc = 0;
        {
            float fx = 0.0f, fy = 0.0f, pox = 0.0f, poy = 0.0f;
            float ax = eax[3], ay = eay[3], ex = eex[3], ey = eey[3];
            if (cnt > 0) {
                float pxv = b1x[(cnt - 1) * TPB];
                float pyv = b1y[(cnt - 1) * TPB];
                float dp  = ex * (pyv - ay) - ey * (pxv - ax);
                #pragma unroll
                for (int k = 0; k < 7; k++) {
                    if (k < cnt) {
                        float cxv = b1x[k * TPB];
                        float cyv = b1y[k * TPB];
                        float dc  = ex * (cyv - ay) - ey * (cxv - ax);
                        bool in_p = (dp >= 0.0f);
                        bool in_c = (dc >= 0.0f);
                        if (in_p != in_c) {
                            float t = dp * fast_rcp(dp - dc);
                            float X = pxv + t * (cxv - pxv);
                            float Y = pyv + t * (cyv - pyv);
                            if (oc == 0) { fx = X; fy = Y; }
                            else         s += pox * Y - poy * X;
                            pox = X; poy = Y; oc++;
                        }
                        if (in_c) {
                            if (oc == 0) { fx = cxv; fy = cyv; }
                            else         s += pox * cyv - poy * cxv;
                            pox = cxv; poy = cyv; oc++;
                        }
                        pxv = cxv; pyv = cyv; dp = dc;
                    }
                }
                if (oc >= 3) s += pox * fy - poy * fx;   // close polygon
            }
        }
        float overlap = (oc >= 3) ? 0.5f * fabsf(s) : 0.0f;

        float iou = overlap * fast_rcp(area1 + area2 - overlap + EPSF);
        iou = fminf(fmaxf(iou, EPSF), 1.0f);
        loss = 1.0f - iou;
    }

    // --- Intra-block reduction ---
    #pragma unroll
    for (int off = 16; off > 0; off >>= 1)
        loss += __shfl_down_sync(0xffffffffu, loss, off);

    __shared__ float wsum[TPB / 32];
    int lane = threadIdx.x & 31;
    int wid  = threadIdx.x >> 5;
    if (lane == 0) wsum[wid] = loss;
    __syncthreads();

    if (wid == 0) {
        float v = (lane < TPB / 32) ? wsum[lane] : 0.0f;
        #pragma unroll
        for (int off = TPB / 64; off > 0; off >>= 1)
            v += __shfl_down_sync(0xffffffffu, v, off);
        if (lane == 0) wsum[0] = v;
    }
    __syncthreads();

    // --- Last-block-done final reduction (single launch) ---
    __shared__ bool is_last;
    if (threadIdx.x == 0) {
        g_partial[blockIdx.x] = wsum[0];
        __threadfence();
        unsigned prev = atomicInc(&g_count, gridDim.x - 1);
        is_last = (prev == gridDim.x - 1);
    }
    __syncthreads();

    if (is_last) {
        double s = 0.0;
        for (int k = threadIdx.x; k < (int)gridDim.x; k += TPB)
            s += (double)g_partial[k];
        #pragma unroll
        for (int off = 16; off > 0; off >>= 1)
            s += __shfl_down_sync(0xffffffffu, s, off);

        __shared__ double dsum[TPB / 32];
        if (lane == 0) dsum[wid] = s;
        __syncthreads();
        if (wid == 0) {
            double v = (lane < TPB / 32) ? dsum[lane] : 0.0;
            #pragma unroll
            for (int off = TPB / 64; off > 0; off >>= 1)
                v += __shfl_down_sync(0xffffffffu, v, off);
            if (lane == 0)
                out[0] = (float)(v / (double)n);
        }
    }
}

extern "C" void kernel_launch(void* const* d_in, const int* in_sizes, int n_in,
                              void* d_out, int out_size) {
    const float* pred = (const float*)d_in[0];
    const float* tgt  = (const float*)d_in[1];
    int n = in_sizes[0] / 8;

    int blocks = (n + TPB - 1) / TPB;
    poly_iou_kernel<<<blocks, TPB>>>(pred, tgt, (float*)d_out, n);
}